// round 7
// baseline (speedup 1.0000x reference)
#include <cuda_runtime.h>
#include <math.h>

// sym_logm of B SPD 64x64 fp32 matrices.
// Kernel 1: one-sided Hestenes Jacobi, one warp per matrix, 2 columns per lane
//   (C0 = col L, C1 = col L+32) register-resident as u64 (f32x2 pairs).
//   Phase A (mm=1..31): XOR pairing (j, j^mm). The C0-round and C1-round are
//   FUSED: dots, angles and rotations of both sides interleaved for 2x ILP in
//   the latency-critical chain. Partner data via two-pass shfl_xor re-fetch
//   (no buffer). No min-blocks cap -> no spill; ~2 CTAs/SM.
//   Cross phase (k=0..31): lane-local pairs (C0,C1); C1 ring-shifts per round.
// Kernel 2: out[b] = sum_k w_k g_k g_k^T via scratch P,Q.

#define MAXB 8192
#define NMAT 64
#define FULLM 0xffffffffu
// rotation threshold on apq^2: |apq| > 2e-5 * sqrt(np*nq)
#define TH2 4e-10f
typedef unsigned long long u64;

__device__ float g_P[(size_t)MAXB * NMAT * NMAT];
__device__ float g_Q[(size_t)MAXB * NMAT * NMAT];

__device__ __forceinline__ u64 pk(float lo, float hi) {
    u64 r; asm("mov.b64 %0,{%1,%2};" : "=l"(r) : "f"(lo), "f"(hi)); return r;
}
__device__ __forceinline__ void upk(u64 v, float& lo, float& hi) {
    asm("mov.b64 {%0,%1},%2;" : "=f"(lo), "=f"(hi) : "l"(v));
}
__device__ __forceinline__ u64 fma2_(u64 a, u64 b, u64 c) {
    u64 d; asm("fma.rn.f32x2 %0,%1,%2,%3;" : "=l"(d) : "l"(a), "l"(b), "l"(c)); return d;
}
__device__ __forceinline__ u64 mul2_(u64 a, u64 b) {
    u64 d; asm("mul.rn.f32x2 %0,%1,%2;" : "=l"(d) : "l"(a), "l"(b)); return d;
}

__global__ __launch_bounds__(128) void jacobi_xor(const float* __restrict__ X, int B)
{
    const int warp = blockIdx.x * (blockDim.x >> 5) + (threadIdx.x >> 5);
    if (warp >= B) return;
    const int lane = threadIdx.x & 31;

    // C0 = column lane, C1 = column lane+32 (X symmetric: column c == row c).
    u64 C0[32], C1[32];
    {
        const float4* x4 = (const float4*)(X + (size_t)warp * 4096);
        #pragma unroll
        for (int r = 0; r < 16; ++r) {
            float4 v = x4[lane * 16 + r];
            C0[2*r]   = pk(v.x, v.y); C0[2*r+1] = pk(v.z, v.w);
            float4 w = x4[(lane + 32) * 16 + r];
            C1[2*r]   = pk(w.x, w.y); C1[2*r+1] = pk(w.z, w.w);
        }
    }

    float n0, n1;
    {
        u64 a0 = 0, a1 = 0;
        #pragma unroll
        for (int j = 0; j < 32; ++j) { a0 = fma2_(C0[j], C0[j], a0); a1 = fma2_(C1[j], C1[j], a1); }
        float lo, hi; upk(a0, lo, hi); n0 = lo + hi; upk(a1, lo, hi); n1 = lo + hi;
    }

    for (int sweep = 0; sweep < 28; ++sweep) {
        int any = 0;

        // ---- Phase A: XOR pairs, BOTH slots fused per round ----
        #pragma unroll 1
        for (int mm = 1; mm < 32; ++mm) {
            const bool amP = (lane < (lane ^ mm));

            // pass 1: fetch + dot, both sides interleaved (8 FMA chains)
            u64 a0 = 0, a1 = 0, b0 = 0, b1 = 0;
            #pragma unroll
            for (int j = 0; j < 32; j += 2) {
                u64 r00 = __shfl_xor_sync(FULLM, C0[j],   mm);
                u64 r01 = __shfl_xor_sync(FULLM, C0[j+1], mm);
                u64 r10 = __shfl_xor_sync(FULLM, C1[j],   mm);
                u64 r11 = __shfl_xor_sync(FULLM, C1[j+1], mm);
                a0 = fma2_(C0[j],   r00, a0);
                a1 = fma2_(C0[j+1], r01, a1);
                b0 = fma2_(C1[j],   r10, b0);
                b1 = fma2_(C1[j+1], r11, b1);
            }
            float l0, h0, l1, h1;
            upk(a0, l0, h0); upk(a1, l1, h1);
            float apqA = (l0 + h0) + (l1 + h1);      // bit-identical on both partners
            upk(b0, l0, h0); upk(b1, l1, h1);
            float apqB = (l0 + h0) + (l1 + h1);

            float pnA = __shfl_xor_sync(FULLM, n0, mm);
            float pnB = __shfl_xor_sync(FULLM, n1, mm);

            bool rotA = (apqA * apqA > TH2 * n0 * pnA);
            bool rotB = (apqB * apqB > TH2 * n1 * pnB);
            if (__any_sync(FULLM, rotA | rotB)) {
                any = 1;
                // angles: two independent MUFU chains, overlap
                float cA = 1.0f, seA = 0.0f;
                if (rotA) {
                    float np = amP ? n0 : pnA, nq = amP ? pnA : n0;
                    float th = 0.5f * (nq - np) / apqA;
                    float t  = copysignf(1.0f, th) / (fabsf(th) + sqrtf(fmaf(th, th, 1.0f)));
                    cA = rsqrtf(fmaf(t, t, 1.0f));
                    float s = t * cA;
                    seA = amP ? -s : s;
                    n0  = fmaf(amP ? -t : t, apqA, n0);
                }
                float cB = 1.0f, seB = 0.0f;
                if (rotB) {
                    float np = amP ? n1 : pnB, nq = amP ? pnB : n1;
                    float th = 0.5f * (nq - np) / apqB;
                    float t  = copysignf(1.0f, th) / (fabsf(th) + sqrtf(fmaf(th, th, 1.0f)));
                    cB = rsqrtf(fmaf(t, t, 1.0f));
                    float s = t * cB;
                    seB = amP ? -s : s;
                    n1  = fmaf(amP ? -t : t, apqB, n1);
                }
                u64 cA2 = pk(cA, cA), seA2 = pk(seA, seA);
                u64 cB2 = pk(cB, cB), seB2 = pk(seB, seB);

                // pass 2: re-fetch partner values (C unmodified since pass 1;
                // within an iteration the shfl reads the pre-write value), rotate.
                #pragma unroll
                for (int j = 0; j < 32; ++j) {
                    u64 r0 = __shfl_xor_sync(FULLM, C0[j], mm);
                    u64 r1 = __shfl_xor_sync(FULLM, C1[j], mm);
                    C0[j] = fma2_(cA2, C0[j], mul2_(seA2, r0));  // exact no-op if c=1,se=0
                    C1[j] = fma2_(cB2, C1[j], mul2_(seB2, r1));
                }
            }
        }

        // ---- Cross phase: lane-local pairs (C0, C1); ring-shift C1 each round ----
        #pragma unroll 1
        for (int k = 0; k < 32; ++k) {
            u64 a0 = 0, a1 = 0, a2 = 0, a3 = 0;
            #pragma unroll
            for (int j = 0; j < 32; j += 4) {
                a0 = fma2_(C0[j],   C1[j],   a0);
                a1 = fma2_(C0[j+1], C1[j+1], a1);
                a2 = fma2_(C0[j+2], C1[j+2], a2);
                a3 = fma2_(C0[j+3], C1[j+3], a3);
            }
            float l0, h0, l1, h1, l2, h2, l3, h3;
            upk(a0, l0, h0); upk(a1, l1, h1); upk(a2, l2, h2); upk(a3, l3, h3);
            float apq = ((l0 + h0) + (l1 + h1)) + ((l2 + h2) + (l3 + h3));

            bool rot = (apq * apq > TH2 * n0 * n1);
            if (__any_sync(FULLM, rot)) {
                float c = 1.0f, s = 0.0f;
                if (rot) {
                    float th = 0.5f * (n1 - n0) / apq;   // C0 is always p (lower index)
                    float t  = copysignf(1.0f, th) / (fabsf(th) + sqrtf(fmaf(th, th, 1.0f)));
                    c = rsqrtf(fmaf(t, t, 1.0f));
                    s = t * c;
                    n0 = fmaf(-t, apq, n0);
                    n1 = fmaf( t, apq, n1);
                    any = 1;
                }
                u64 c2 = pk(c, c), s2 = pk(s, s), ns2 = pk(-s, -s);
                #pragma unroll
                for (int j = 0; j < 32; ++j) {
                    u64 x = C0[j];
                    C0[j] = fma2_(c2, x, mul2_(ns2, C1[j]));
                    C1[j] = fma2_(s2, x, mul2_(c2,  C1[j]));
                }
            }
            // ring-shift slot-1 column (and its norm) to the previous lane
            #pragma unroll
            for (int j = 0; j < 32; ++j) C1[j] = __shfl_sync(FULLM, C1[j], lane + 1);
            n1 = __shfl_sync(FULLM, n1, lane + 1);
        }

        if (!__any_sync(FULLM, any)) break;

        // exact norm refresh (kills analytic-carry drift)
        u64 a0 = 0, a1 = 0;
        #pragma unroll
        for (int j = 0; j < 32; ++j) { a0 = fma2_(C0[j], C0[j], a0); a1 = fma2_(C1[j], C1[j], a1); }
        float lo, hi; upk(a0, lo, hi); n0 = lo + hi; upk(a1, lo, hi); n1 = lo + hi;
    }

    // exact norms -> weights w = log(lambda)/lambda^2 = 0.5*log(n)/n
    float e0, e1;
    {
        u64 a0 = 0, a1 = 0;
        #pragma unroll
        for (int j = 0; j < 32; ++j) { a0 = fma2_(C0[j], C0[j], a0); a1 = fma2_(C1[j], C1[j], a1); }
        float lo, hi; upk(a0, lo, hi); e0 = lo + hi; upk(a1, lo, hi); e1 = lo + hi;
    }
    float w0 = 0.5f * logf(fmaxf(e0, 1e-30f)) / e0;
    float w1 = 0.5f * logf(fmaxf(e1, 1e-30f)) / e1;
    u64 w02 = pk(w0, w0), w12 = pk(w1, w1);

    // Store P = columns, Q = w * columns. Layout [b][col][row], rows contiguous.
    u64* Pp = (u64*)(g_P + (size_t)warp * 4096);
    u64* Qp = (u64*)(g_Q + (size_t)warp * 4096);
    #pragma unroll
    for (int j = 0; j < 32; ++j) {
        Pp[lane * 32 + j]        = C0[j];  Qp[lane * 32 + j]        = mul2_(w02, C0[j]);
        Pp[(lane + 32) * 32 + j] = C1[j];  Qp[(lane + 32) * 32 + j] = mul2_(w12, C1[j]);
    }
}

// out[b][i][j] = sum_k P[b][k][i] * Q[b][k][j]
__global__ __launch_bounds__(256) void gram_epilogue(float* __restrict__ out, int B)
{
    __shared__ float Ps[NMAT * NMAT];
    __shared__ float Qs[NMAT * NMAT];
    const int b = blockIdx.x;
    const int tid = threadIdx.x;
    const float* Pb = g_P + (size_t)b * (NMAT * NMAT);
    const float* Qb = g_Q + (size_t)b * (NMAT * NMAT);

    #pragma unroll
    for (int i = tid; i < NMAT * NMAT; i += 256) {
        Ps[i] = Pb[i];
        Qs[i] = Qb[i];
    }
    __syncthreads();

    const int ti = tid >> 6;
    const int tj = tid & 63;
    float acc[16];
    #pragma unroll
    for (int r = 0; r < 16; ++r) acc[r] = 0.0f;

    #pragma unroll 4
    for (int k = 0; k < NMAT; ++k) {
        float qv = Qs[k * NMAT + tj];
        const float4* prow = (const float4*)&Ps[k * NMAT + ti * 16];
        #pragma unroll
        for (int r4 = 0; r4 < 4; ++r4) {
            float4 p = prow[r4];
            acc[4*r4+0] = fmaf(p.x, qv, acc[4*r4+0]);
            acc[4*r4+1] = fmaf(p.y, qv, acc[4*r4+1]);
            acc[4*r4+2] = fmaf(p.z, qv, acc[4*r4+2]);
            acc[4*r4+3] = fmaf(p.w, qv, acc[4*r4+3]);
        }
    }

    float* Ob = out + (size_t)b * (NMAT * NMAT);
    #pragma unroll
    for (int r = 0; r < 16; ++r)
        Ob[(ti * 16 + r) * NMAT + tj] = acc[r];
}

extern "C" void kernel_launch(void* const* d_in, const int* in_sizes, int n_in,
                              void* d_out, int out_size) {
    const float* X = (const float*)d_in[0];
    float* out = (float*)d_out;
    int B = in_sizes[0] / (NMAT * NMAT);
    if (B > MAXB) B = MAXB;
    int blocks = (B + 3) / 4;
    jacobi_xor<<<blocks, 128>>>(X, B);
    gram_epilogue<<<B, 256>>>(out, B);
}

// round 8
// speedup vs baseline: 1.0830x; 1.0830x over previous
#include <cuda_runtime.h>
#include <math.h>

// sym_logm of B SPD 64x64 fp32 matrices.
// Kernel 1: one-sided Hestenes Jacobi, ONE WARP PER BLOCK (independent
//   retirement -> no CTA-mate tail wait), 2 columns per lane (C0 = col L,
//   C1 = col L+32) register-resident as u64 (f32x2 pairs).
//   Phase A (mm=1..31): XOR pairing (j, j^mm); buffered single-pass partner
//   fetch (64 SHFL.32/side) reused for dot AND rotation.
//   Cross phase (k=0..31): lane-local pairs (C0,C1); C1 ring-shifts per round.
// Kernel 2: out[b] = sum_k w_k g_k g_k^T via scratch P,Q.

#define MAXB 8192
#define NMAT 64
#define FULLM 0xffffffffu
// rotation threshold on apq^2: |apq| > 2e-5 * sqrt(np*nq)  (validated 6.2e-5 rel_err)
#define TH2 4e-10f
typedef unsigned long long u64;

__device__ float g_P[(size_t)MAXB * NMAT * NMAT];
__device__ float g_Q[(size_t)MAXB * NMAT * NMAT];

__device__ __forceinline__ u64 pk(float lo, float hi) {
    u64 r; asm("mov.b64 %0,{%1,%2};" : "=l"(r) : "f"(lo), "f"(hi)); return r;
}
__device__ __forceinline__ void upk(u64 v, float& lo, float& hi) {
    asm("mov.b64 {%0,%1},%2;" : "=f"(lo), "=f"(hi) : "l"(v));
}
__device__ __forceinline__ u64 fma2_(u64 a, u64 b, u64 c) {
    u64 d; asm("fma.rn.f32x2 %0,%1,%2,%3;" : "=l"(d) : "l"(a), "l"(b), "l"(c)); return d;
}
__device__ __forceinline__ u64 mul2_(u64 a, u64 b) {
    u64 d; asm("mul.rn.f32x2 %0,%1,%2;" : "=l"(d) : "l"(a), "l"(b)); return d;
}

// One pair-side of a Phase-A round: buffered single-pass (fetch once, reuse).
__device__ __forceinline__ int sideA(u64* C, float& n, int mm, bool amP)
{
    u64 R[32];
    #pragma unroll
    for (int j = 0; j < 32; ++j) R[j] = __shfl_xor_sync(FULLM, C[j], mm);

    u64 a0 = 0, a1 = 0;
    #pragma unroll
    for (int j = 0; j < 32; j += 2) {
        a0 = fma2_(C[j],   R[j],   a0);
        a1 = fma2_(C[j+1], R[j+1], a1);
    }
    float l0, h0, l1, h1; upk(a0, l0, h0); upk(a1, l1, h1);
    float apq = (l0 + h0) + (l1 + h1);         // bit-identical on both partners
    float pn  = __shfl_xor_sync(FULLM, n, mm); // partner's norm

    bool rot = (apq * apq > TH2 * n * pn);
    int active = (int)__any_sync(FULLM, rot);
    if (active) {
        float c = 1.0f, se = 0.0f;
        if (rot) {
            float np = amP ? n  : pn;
            float nq = amP ? pn : n;
            float th = 0.5f * (nq - np) / apq;
            float t  = copysignf(1.0f, th) / (fabsf(th) + sqrtf(fmaf(th, th, 1.0f)));
            c = rsqrtf(fmaf(t, t, 1.0f));
            float s = t * c;
            se = amP ? -s : s;                 // p: c*own - s*other ; q: c*own + s*other
            n  = fmaf(amP ? -t : t, apq, n);
        }
        u64 c2 = pk(c, c), se2 = pk(se, se);
        #pragma unroll
        for (int j = 0; j < 32; ++j)
            C[j] = fma2_(c2, C[j], mul2_(se2, R[j]));   // exact no-op when c=1,se=0
    }
    return active;
}

__global__ __launch_bounds__(32) void jacobi_xor(const float* __restrict__ X, int B)
{
    const int warp = blockIdx.x;
    if (warp >= B) return;
    const int lane = threadIdx.x & 31;

    // C0 = column lane, C1 = column lane+32 (X symmetric: column c == row c).
    u64 C0[32], C1[32];
    {
        const float4* x4 = (const float4*)(X + (size_t)warp * 4096);
        #pragma unroll
        for (int r = 0; r < 16; ++r) {
            float4 v = x4[lane * 16 + r];
            C0[2*r]   = pk(v.x, v.y); C0[2*r+1] = pk(v.z, v.w);
            float4 w = x4[(lane + 32) * 16 + r];
            C1[2*r]   = pk(w.x, w.y); C1[2*r+1] = pk(w.z, w.w);
        }
    }

    float n0, n1;
    {
        u64 a0 = 0, a1 = 0;
        #pragma unroll
        for (int j = 0; j < 32; ++j) { a0 = fma2_(C0[j], C0[j], a0); a1 = fma2_(C1[j], C1[j], a1); }
        float lo, hi; upk(a0, lo, hi); n0 = lo + hi; upk(a1, lo, hi); n1 = lo + hi;
    }

    for (int sweep = 0; sweep < 28; ++sweep) {
        int any = 0;

        // ---- Phase A: XOR pairs within each slot ----
        #pragma unroll 1
        for (int mm = 1; mm < 32; ++mm) {
            bool amP = (lane < (lane ^ mm));
            any |= sideA(C0, n0, mm, amP);
            any |= sideA(C1, n1, mm, amP);
        }

        // ---- Cross phase: lane-local pairs (C0, C1); ring-shift C1 each round ----
        #pragma unroll 1
        for (int k = 0; k < 32; ++k) {
            u64 a0 = 0, a1 = 0;
            #pragma unroll
            for (int j = 0; j < 32; j += 2) {
                a0 = fma2_(C0[j],   C1[j],   a0);
                a1 = fma2_(C0[j+1], C1[j+1], a1);
            }
            float l0, h0, l1, h1; upk(a0, l0, h0); upk(a1, l1, h1);
            float apq = (l0 + h0) + (l1 + h1);

            bool rot = (apq * apq > TH2 * n0 * n1);
            if (__any_sync(FULLM, rot)) {
                float c = 1.0f, s = 0.0f;
                if (rot) {
                    float th = 0.5f * (n1 - n0) / apq;   // C0 is always p (lower index)
                    float t  = copysignf(1.0f, th) / (fabsf(th) + sqrtf(fmaf(th, th, 1.0f)));
                    c = rsqrtf(fmaf(t, t, 1.0f));
                    s = t * c;
                    n0 = fmaf(-t, apq, n0);
                    n1 = fmaf( t, apq, n1);
                    any = 1;
                }
                u64 c2 = pk(c, c), s2 = pk(s, s), ns2 = pk(-s, -s);
                #pragma unroll
                for (int j = 0; j < 32; ++j) {
                    u64 x = C0[j];
                    C0[j] = fma2_(c2, x, mul2_(ns2, C1[j]));
                    C1[j] = fma2_(s2, x, mul2_(c2,  C1[j]));
                }
            }
            // ring-shift slot-1 column (and its norm) to the previous lane
            #pragma unroll
            for (int j = 0; j < 32; ++j) C1[j] = __shfl_sync(FULLM, C1[j], lane + 1);
            n1 = __shfl_sync(FULLM, n1, lane + 1);
        }

        if (!__any_sync(FULLM, any)) break;

        // exact norm refresh (kills analytic-carry drift)
        u64 a0 = 0, a1 = 0;
        #pragma unroll
        for (int j = 0; j < 32; ++j) { a0 = fma2_(C0[j], C0[j], a0); a1 = fma2_(C1[j], C1[j], a1); }
        float lo, hi; upk(a0, lo, hi); n0 = lo + hi; upk(a1, lo, hi); n1 = lo + hi;
    }

    // exact norms -> weights w = log(lambda)/lambda^2 = 0.5*log(n)/n
    float e0, e1;
    {
        u64 a0 = 0, a1 = 0;
        #pragma unroll
        for (int j = 0; j < 32; ++j) { a0 = fma2_(C0[j], C0[j], a0); a1 = fma2_(C1[j], C1[j], a1); }
        float lo, hi; upk(a0, lo, hi); e0 = lo + hi; upk(a1, lo, hi); e1 = lo + hi;
    }
    float w0 = 0.5f * logf(fmaxf(e0, 1e-30f)) / e0;
    float w1 = 0.5f * logf(fmaxf(e1, 1e-30f)) / e1;
    u64 w02 = pk(w0, w0), w12 = pk(w1, w1);

    // Store P = columns, Q = w * columns. Layout [b][col][row], rows contiguous.
    u64* Pp = (u64*)(g_P + (size_t)warp * 4096);
    u64* Qp = (u64*)(g_Q + (size_t)warp * 4096);
    #pragma unroll
    for (int j = 0; j < 32; ++j) {
        Pp[lane * 32 + j]        = C0[j];  Qp[lane * 32 + j]        = mul2_(w02, C0[j]);
        Pp[(lane + 32) * 32 + j] = C1[j];  Qp[(lane + 32) * 32 + j] = mul2_(w12, C1[j]);
    }
}

// out[b][i][j] = sum_k P[b][k][i] * Q[b][k][j]
__global__ __launch_bounds__(256) void gram_epilogue(float* __restrict__ out, int B)
{
    __shared__ float Ps[NMAT * NMAT];
    __shared__ float Qs[NMAT * NMAT];
    const int b = blockIdx.x;
    const int tid = threadIdx.x;
    const float* Pb = g_P + (size_t)b * (NMAT * NMAT);
    const float* Qb = g_Q + (size_t)b * (NMAT * NMAT);

    #pragma unroll
    for (int i = tid; i < NMAT * NMAT; i += 256) {
        Ps[i] = Pb[i];
        Qs[i] = Qb[i];
    }
    __syncthreads();

    const int ti = tid >> 6;
    const int tj = tid & 63;
    float acc[16];
    #pragma unroll
    for (int r = 0; r < 16; ++r) acc[r] = 0.0f;

    #pragma unroll 4
    for (int k = 0; k < NMAT; ++k) {
        float qv = Qs[k * NMAT + tj];
        const float4* prow = (const float4*)&Ps[k * NMAT + ti * 16];
        #pragma unroll
        for (int r4 = 0; r4 < 4; ++r4) {
            float4 p = prow[r4];
            acc[4*r4+0] = fmaf(p.x, qv, acc[4*r4+0]);
            acc[4*r4+1] = fmaf(p.y, qv, acc[4*r4+1]);
            acc[4*r4+2] = fmaf(p.z, qv, acc[4*r4+2]);
            acc[4*r4+3] = fmaf(p.w, qv, acc[4*r4+3]);
        }
    }

    float* Ob = out + (size_t)b * (NMAT * NMAT);
    #pragma unroll
    for (int r = 0; r < 16; ++r)
        Ob[(ti * 16 + r) * NMAT + tj] = acc[r];
}

extern "C" void kernel_launch(void* const* d_in, const int* in_sizes, int n_in,
                              void* d_out, int out_size) {
    const float* X = (const float*)d_in[0];
    float* out = (float*)d_out;
    int B = in_sizes[0] / (NMAT * NMAT);
    if (B > MAXB) B = MAXB;
    jacobi_xor<<<B, 32>>>(X, B);
    gram_epilogue<<<B, 256>>>(out, B);
}